// round 5
// baseline (speedup 1.0000x reference)
#include <cuda_runtime.h>
#include <cstdint>

typedef unsigned long long ull;
#define NROWS 8192
#define NHID  64
#define NEMB  256

__device__ float  g_h[NROWS * NHID];
__device__ float2 g_fsp[NROWS];   // (f_src+b, exp(f_src+b))
__device__ float2 g_fdp[NROWS];   // (f_dst,   exp(f_dst))
__device__ int    g_cnt[NROWS];
__device__ int    g_R[NROWS];
__device__ uint4  g_bits4[NROWS * 64];

__device__ __forceinline__ ull packf2(float lo, float hi) {
    ull r;
    asm("mov.b64 %0, {%1, %2};" : "=l"(r) : "r"(__float_as_uint(lo)), "r"(__float_as_uint(hi)));
    return r;
}
__device__ __forceinline__ void unpackf2(float& lo, float& hi, ull v) {
    unsigned a, b;
    asm("mov.b64 {%0, %1}, %2;" : "=r"(a), "=r"(b) : "l"(v));
    lo = __uint_as_float(a); hi = __uint_as_float(b);
}
__device__ __forceinline__ void fma2(ull& d, ull a, ull b) {
    asm("fma.rn.f32x2 %0, %1, %2, %0;" : "+l"(d) : "l"(a), "l"(b));
}
__device__ __forceinline__ ull addf2(ull a, ull b) {
    ull d; asm("add.rn.f32x2 %0, %1, %2;" : "=l"(d) : "l"(a), "l"(b)); return d;
}

// ======================= K1: h, f_src, f_dst, exp tables =======================
// grid 512, block 256: 16 rows/block, thread = (r = tid>>6 in 0..3, d = tid&63),
// thread computes rows r, r+4, r+8, r+12.
__global__ void k_h(const float* __restrict__ x, const float* __restrict__ Ww,
                    const float* __restrict__ Wb, const float* __restrict__ a1,
                    const float* __restrict__ a2, const float* __restrict__ ab) {
    __shared__ float xs[16][NEMB];
    __shared__ float s1[16][2], s2[16][2];
    const int tid = threadIdx.x;
    const int r = tid >> 6, d = tid & 63;
    const int base = blockIdx.x * 16;

    {
        const float4* src = (const float4*)(x + (size_t)base * NEMB);
        float4* dst = (float4*)&xs[0][0];
        #pragma unroll
        for (int t = 0; t < 4; t++) dst[tid + t * 256] = __ldg(src + tid + t * 256);
    }
    __syncthreads();

    const float wb = Wb[d];
    float acc[4] = {wb, wb, wb, wb};
    #pragma unroll 4
    for (int k = 0; k < NEMB; k++) {
        const float wv = __ldg(Ww + k * NHID + d);
        acc[0] = fmaf(xs[r][k],      wv, acc[0]);
        acc[1] = fmaf(xs[r + 4][k],  wv, acc[1]);
        acc[2] = fmaf(xs[r + 8][k],  wv, acc[2]);
        acc[3] = fmaf(xs[r + 12][k], wv, acc[3]);
    }
    const float va1 = __ldg(a1 + d), va2 = __ldg(a2 + d);
    const int half = (tid >> 5) & 1;
    #pragma unroll
    for (int i = 0; i < 4; i++) {
        const int row = base + r + 4 * i;
        g_h[(size_t)row * NHID + d] = acc[i];
        float v1 = acc[i] * va1, v2 = acc[i] * va2;
        #pragma unroll
        for (int o = 16; o >= 1; o >>= 1) {
            v1 += __shfl_xor_sync(0xffffffffu, v1, o);
            v2 += __shfl_xor_sync(0xffffffffu, v2, o);
        }
        if ((tid & 31) == 0) { s1[r + 4 * i][half] = v1; s2[r + 4 * i][half] = v2; }
    }
    __syncthreads();
    if (tid < 16) {
        const int row = base + tid;
        float fs = s1[tid][0] + s1[tid][1] + ab[0];
        float fd = s2[tid][0] + s2[tid][1];
        g_fsp[row] = make_float2(fs, expf(fs));
        g_fdp[row] = make_float2(fd, expf(fd));
    }
}

// ======================= K2: bitmask build + per-row counts =======================
__global__ void k_mask(const int* __restrict__ adj) {
    const int w = threadIdx.x >> 5, lane = threadIdx.x & 31;
    const int row = blockIdx.x * 8 + w;
    const int* p = adj + (size_t)row * NROWS;
    int c = 0;
    #pragma unroll 4
    for (int ch = 0; ch < 64; ch++) {
        const int* q = p + ch * 128 + lane;
        unsigned W0 = __ballot_sync(0xffffffffu, __ldg(q)      > 0);
        unsigned W1 = __ballot_sync(0xffffffffu, __ldg(q + 32) > 0);
        unsigned W2 = __ballot_sync(0xffffffffu, __ldg(q + 64) > 0);
        unsigned W3 = __ballot_sync(0xffffffffu, __ldg(q + 96) > 0);
        if (lane == 0) g_bits4[row * 64 + ch] = make_uint4(W0, W1, W2, W3);
        c += __popc(W0) + __popc(W1) + __popc(W2) + __popc(W3);
    }
    if (lane == 0) g_cnt[row] = c;
}

// ======================= K3: exclusive scan of counts =======================
__global__ void k_scan() {
    __shared__ int sums[256];
    const int t = threadIdx.x;
    const int base = t * 32;
    int tot = 0;
    #pragma unroll
    for (int k = 0; k < 32; k++) tot += g_cnt[base + k];
    sums[t] = tot;
    __syncthreads();
    #pragma unroll
    for (int off = 1; off < 256; off <<= 1) {
        int u = (t >= off) ? sums[t - off] : 0;
        __syncthreads();
        sums[t] += u;
        __syncthreads();
    }
    int run = sums[t] - tot;
    #pragma unroll
    for (int k = 0; k < 32; k++) { int c = g_cnt[base + k]; g_R[base + k] = run; run += c; }
}

// ======================= K4: main fused kernel =======================
__device__ __forceinline__ float edgeE(int rr) {
    float2 a  = __ldg(&g_fsp[rr >> 13]);
    float2 bq = __ldg(&g_fdp[rr & (NROWS - 1)]);
    float s = a.x + bq.x;
    float u = 0.01f * s;
    float p = fmaf(u, 0.0416666679f, 0.1666666716f);
    p = fmaf(p, u, 0.5f);
    p = fmaf(p, u, 1.0f);
    p = fmaf(p, u, 1.0f);
    return (s >= 0.0f) ? a.y * bq.y : p;
}

__device__ __forceinline__ void red_store(ull (&acc)[8][4], ull* redu, int slotbase) {
    #pragma unroll
    for (int k = 0; k < 8; k++)
        #pragma unroll
        for (int p = 0; p < 4; p++)
            redu[slotbase + (k * 4 + p) * 32] = acc[k][p];
}
__device__ __forceinline__ void red_add(ull (&acc)[8][4], const ull* redu, int slotbase) {
    #pragma unroll
    for (int k = 0; k < 8; k++)
        #pragma unroll
        for (int p = 0; p < 4; p++)
            acc[k][p] = addf2(acc[k][p], redu[slotbase + (k * 4 + p) * 32]);
}

// dynamic smem: Wt = ull[128][64] (dup slots, 64KB) | hs = ull[128*32] (32KB)
// Wt[c*64 + s] with s = (row + c) & 31 and s+32 both holding pack(w,w) of W[row][c].
__global__ void __launch_bounds__(256, 2)
k_main(float* __restrict__ out) {
    extern __shared__ ull dsm[];
    ull* Wt = dsm;            // 8192 ull
    ull* hs = dsm + 8192;     // 4096 ull (row j: 32 packed pairs)
    __shared__ float sS[32];

    const int tid  = threadIdx.x;
    const int w    = tid >> 5;
    const int lane = tid & 31;
    const int rg   = lane >> 3;    // Phase-B rows: rg + 4k
    const int dg   = lane & 7;     // dims 4dg..4dg+3 and 32+4dg..+3
    const int row0 = blockIdx.x * 32;
    const unsigned ml = (1u << lane) - 1u;

    int   rank[4];
    float sacc[4];
    #pragma unroll
    for (int k = 0; k < 4; k++) { rank[k] = g_R[row0 + 4 * w + k]; sacc[k] = 0.0f; }

    ull acc[8][4];
    #pragma unroll
    for (int k = 0; k < 8; k++)
        #pragma unroll
        for (int p = 0; p < 4; p++) acc[k][p] = 0ull;

    for (int tile = 0; tile < 64; tile++) {
        // ---- h tile [128][64] -> hs (bytes identical to packed-pair layout)
        {
            const float4* hsrc = (const float4*)g_h + (size_t)tile * 2048;
            float4* hdst = (float4*)hs;
            #pragma unroll
            for (int t = 0; t < 8; t++)
                hdst[tid + t * 256] = __ldg(hsrc + tid + t * 256);
        }

        // ---- Phase A: dense dup-packed W tile + ranks + row sums
        #pragma unroll
        for (int k = 0; k < 4; k++) {
            const int il = 4 * w + k;
            uint4 bw = __ldg(g_bits4 + (size_t)(row0 + il) * 64 + tile);
            const int P0 = __popc(bw.x), P1 = __popc(bw.y), P2 = __popc(bw.z);
            const int r0 = rank[k] + __popc(bw.x & ml);
            const int r1 = rank[k] + P0 + __popc(bw.y & ml);
            const int r2 = rank[k] + P0 + P1 + __popc(bw.z & ml);
            const int r3 = rank[k] + P0 + P1 + P2 + __popc(bw.w & ml);
            rank[k] += P0 + P1 + P2 + __popc(bw.w);
            float w0 = 0.f, w1 = 0.f, w2 = 0.f, w3 = 0.f, sl = 0.f;
            if ((bw.x >> lane) & 1) { w0 = edgeE(r0); sl += w0; }
            if ((bw.y >> lane) & 1) { w1 = edgeE(r1); sl += w1; }
            if ((bw.z >> lane) & 1) { w2 = edgeE(r2); sl += w2; }
            if ((bw.w >> lane) & 1) { w3 = edgeE(r3); sl += w3; }
            sacc[k] += sl;
            const ull d0 = packf2(w0, w0), d1 = packf2(w1, w1);
            const ull d2 = packf2(w2, w2), d3 = packf2(w3, w3);
            // columns c = 32q + lane; slot = (il + lane) & 31, duplicated at +32
            ull* wp = Wt + lane * 64 + ((il + lane) & 31);
            wp[0]         = d0; wp[32]        = d0;
            wp[2048]      = d1; wp[2048 + 32] = d1;
            wp[4096]      = d2; wp[4096 + 32] = d2;
            wp[6144]      = d3; wp[6144 + 32] = d3;
        }
        __syncthreads();

        // ---- Phase B: out(32x64) += W(32x128) @ h(128x64), all-LDS packed operands
        {
            const ull* hp = hs + w * 32 + 2 * dg;   // row j = w, this thread's dims
            #pragma unroll
            for (int t = 0; t < 16; t++) {
                const int j = w + 8 * t;
                const ull* wp = Wt + j * 64 + ((rg + j) & 31);  // +4k hits slot or dup
                const ulonglong2 hA = *(const ulonglong2*)(hp);
                const ulonglong2 hB = *(const ulonglong2*)(hp + 16);
                #pragma unroll
                for (int k = 0; k < 8; k++) {
                    const ull wv = wp[4 * k];
                    fma2(acc[k][0], wv, hA.x);
                    fma2(acc[k][1], wv, hA.y);
                    fma2(acc[k][2], wv, hB.x);
                    fma2(acc[k][3], wv, hB.y);
                }
                hp += 8 * 32;
            }
        }
        __syncthreads();
    }

    // ---- per-row softmax denominators (rows 4w+k)
    #pragma unroll
    for (int k = 0; k < 4; k++) {
        float sv = sacc[k];
        #pragma unroll
        for (int o = 16; o >= 1; o >>= 1) sv += __shfl_xor_sync(0xffffffffu, sv, o);
        if (lane == 0) sS[4 * w + k] = sv;
    }
    __syncthreads();

    // ---- tree-reduce 8 j-phase partials in smem (Wt region, 4096 ull used)
    ull* redu = dsm;
    if (w >= 4) red_store(acc, redu, (w - 4) * 1024 + lane);
    __syncthreads();
    if (w < 4)  red_add(acc, redu, w * 1024 + lane);
    __syncthreads();
    if (w == 2 || w == 3) red_store(acc, redu, (w - 2) * 1024 + lane);
    __syncthreads();
    if (w < 2)  red_add(acc, redu, w * 1024 + lane);
    __syncthreads();
    if (w == 1) red_store(acc, redu, lane);
    __syncthreads();

    if (w == 0) {
        red_add(acc, redu, lane);
        #pragma unroll
        for (int k = 0; k < 8; k++) {
            const int row = rg + 4 * k;
            const float sinv = 1.0f / sS[row];
            float v[8];
            unpackf2(v[0], v[1], acc[k][0]);
            unpackf2(v[2], v[3], acc[k][1]);
            unpackf2(v[4], v[5], acc[k][2]);
            unpackf2(v[6], v[7], acc[k][3]);
            float o[8];
            #pragma unroll
            for (int c = 0; c < 8; c++) {
                float t = v[c] * sinv;
                o[c] = (t > 0.0f) ? t : expm1f(t);
            }
            float* op = out + (size_t)(row0 + row) * NHID;
            *(float4*)(op + dg * 4)      = make_float4(o[0], o[1], o[2], o[3]);
            *(float4*)(op + 32 + dg * 4) = make_float4(o[4], o[5], o[6], o[7]);
        }
    }
}

extern "C" void kernel_launch(void* const* d_in, const int* in_sizes, int n_in,
                              void* d_out, int out_size) {
    (void)in_sizes; (void)n_in; (void)out_size;
    const float* x   = (const float*)d_in[0];
    const int*   adj = (const int*)d_in[1];
    const float* Ww  = (const float*)d_in[2];
    const float* Wb  = (const float*)d_in[3];
    const float* a1  = (const float*)d_in[4];
    const float* a2  = (const float*)d_in[5];
    const float* ab  = (const float*)d_in[6];
    float* out = (float*)d_out;

    static int smem_set = 0;
    if (!smem_set) {
        cudaFuncSetAttribute(k_main, cudaFuncAttributeMaxDynamicSharedMemorySize, 98304);
        smem_set = 1;
    }

    k_h   <<<NROWS / 16, 256>>>(x, Ww, Wb, a1, a2, ab);
    k_mask<<<NROWS / 8, 256>>>(adj);
    k_scan<<<1, 256>>>();
    k_main<<<NROWS / 32, 256, 98304>>>(out);
}

// round 6
// speedup vs baseline: 1.1400x; 1.1400x over previous
#include <cuda_runtime.h>
#include <cstdint>

typedef unsigned long long ull;
#define NROWS 8192
#define NHID  64
#define NEMB  256

__device__ float    g_h[NROWS * NHID];
__device__ float2   g_fsp[NROWS];   // (f_src+b, exp(f_src+b))
__device__ float2   g_fdp[NROWS];   // (f_dst,   exp(f_dst))
__device__ int      g_cnt[NROWS];
__device__ int      g_R[NROWS];
__device__ unsigned g_bits[NROWS * 256];  // word w of row r: columns 32w..32w+31

__device__ __forceinline__ ull packf2(float lo, float hi) {
    ull r;
    asm("mov.b64 %0, {%1, %2};" : "=l"(r) : "r"(__float_as_uint(lo)), "r"(__float_as_uint(hi)));
    return r;
}
__device__ __forceinline__ void unpackf2(float& lo, float& hi, ull v) {
    unsigned a, b;
    asm("mov.b64 {%0, %1}, %2;" : "=r"(a), "=r"(b) : "l"(v));
    lo = __uint_as_float(a); hi = __uint_as_float(b);
}
__device__ __forceinline__ void fma2(ull& d, ull a, ull b) {
    asm("fma.rn.f32x2 %0, %1, %2, %0;" : "+l"(d) : "l"(a), "l"(b));
}
__device__ __forceinline__ ull addf2(ull a, ull b) {
    ull d; asm("add.rn.f32x2 %0, %1, %2;" : "=l"(d) : "l"(a), "l"(b)); return d;
}
__device__ __forceinline__ void cpasync16(unsigned saddr, const void* gptr) {
    asm volatile("cp.async.cg.shared.global [%0], [%1], 16;" :: "r"(saddr), "l"(gptr));
}
#define CP_COMMIT() asm volatile("cp.async.commit_group;")
#define CP_WAIT0()  asm volatile("cp.async.wait_group 0;")

// ======================= K1: h, f_src, f_dst, exp tables =======================
__global__ void k_h(const float* __restrict__ x, const float* __restrict__ Ww,
                    const float* __restrict__ Wb, const float* __restrict__ a1,
                    const float* __restrict__ a2, const float* __restrict__ ab) {
    __shared__ float xs[16][NEMB];
    __shared__ float s1[16][2], s2[16][2];
    const int tid = threadIdx.x;
    const int r = tid >> 6, d = tid & 63;
    const int base = blockIdx.x * 16;

    {
        const float4* src = (const float4*)(x + (size_t)base * NEMB);
        float4* dst = (float4*)&xs[0][0];
        #pragma unroll
        for (int t = 0; t < 4; t++) dst[tid + t * 256] = __ldg(src + tid + t * 256);
    }
    __syncthreads();

    const float wb = Wb[d];
    float acc[4] = {wb, wb, wb, wb};
    #pragma unroll 4
    for (int k = 0; k < NEMB; k++) {
        const float wv = __ldg(Ww + k * NHID + d);
        acc[0] = fmaf(xs[r][k],      wv, acc[0]);
        acc[1] = fmaf(xs[r + 4][k],  wv, acc[1]);
        acc[2] = fmaf(xs[r + 8][k],  wv, acc[2]);
        acc[3] = fmaf(xs[r + 12][k], wv, acc[3]);
    }
    const float va1 = __ldg(a1 + d), va2 = __ldg(a2 + d);
    const int half = (tid >> 5) & 1;
    #pragma unroll
    for (int i = 0; i < 4; i++) {
        const int row = base + r + 4 * i;
        g_h[(size_t)row * NHID + d] = acc[i];
        float v1 = acc[i] * va1, v2 = acc[i] * va2;
        #pragma unroll
        for (int o = 16; o >= 1; o >>= 1) {
            v1 += __shfl_xor_sync(0xffffffffu, v1, o);
            v2 += __shfl_xor_sync(0xffffffffu, v2, o);
        }
        if ((tid & 31) == 0) { s1[r + 4 * i][half] = v1; s2[r + 4 * i][half] = v2; }
    }
    __syncthreads();
    if (tid < 16) {
        const int row = base + tid;
        float fs = s1[tid][0] + s1[tid][1] + ab[0];
        float fd = s2[tid][0] + s2[tid][1];
        g_fsp[row] = make_float2(fs, expf(fs));
        g_fdp[row] = make_float2(fd, expf(fd));
    }
}

// ======================= K2: bitmask build + per-row counts =======================
__global__ void k_mask(const int* __restrict__ adj) {
    const int w = threadIdx.x >> 5, lane = threadIdx.x & 31;
    const int row = blockIdx.x * 8 + w;
    const int* p = adj + (size_t)row * NROWS;
    int c = 0;
    #pragma unroll 4
    for (int ch = 0; ch < 64; ch++) {
        const int* q = p + ch * 128 + lane;
        unsigned W0 = __ballot_sync(0xffffffffu, __ldg(q)      > 0);
        unsigned W1 = __ballot_sync(0xffffffffu, __ldg(q + 32) > 0);
        unsigned W2 = __ballot_sync(0xffffffffu, __ldg(q + 64) > 0);
        unsigned W3 = __ballot_sync(0xffffffffu, __ldg(q + 96) > 0);
        if (lane == 0)
            *(uint4*)(g_bits + row * 256 + ch * 4) = make_uint4(W0, W1, W2, W3);
        c += __popc(W0) + __popc(W1) + __popc(W2) + __popc(W3);
    }
    if (lane == 0) g_cnt[row] = c;
}

// ======================= K3: exclusive scan of counts =======================
__global__ void k_scan() {
    __shared__ int sums[256];
    const int t = threadIdx.x;
    const int base = t * 32;
    int tot = 0;
    #pragma unroll
    for (int k = 0; k < 32; k++) tot += g_cnt[base + k];
    sums[t] = tot;
    __syncthreads();
    #pragma unroll
    for (int off = 1; off < 256; off <<= 1) {
        int u = (t >= off) ? sums[t - off] : 0;
        __syncthreads();
        sums[t] += u;
        __syncthreads();
    }
    int run = sums[t] - tot;
    #pragma unroll
    for (int k = 0; k < 32; k++) { int c = g_cnt[base + k]; g_R[base + k] = run; run += c; }
}

// ======================= K4: main fused kernel =======================
__device__ __forceinline__ float edgeE(int rr) {
    float2 a  = __ldg(&g_fsp[rr >> 13]);
    float2 bq = __ldg(&g_fdp[rr & (NROWS - 1)]);
    float s = a.x + bq.x;
    float u = 0.01f * s;
    float p = fmaf(u, 0.0416666679f, 0.1666666716f);
    p = fmaf(p, u, 0.5f);
    p = fmaf(p, u, 1.0f);
    p = fmaf(p, u, 1.0f);
    return (s >= 0.0f) ? a.y * bq.y : p;
}

__device__ __forceinline__ void red_store(ull (&acc)[8][4], ull* redu, int slotbase) {
    #pragma unroll
    for (int k = 0; k < 8; k++)
        #pragma unroll
        for (int p = 0; p < 4; p++)
            redu[slotbase + (k * 4 + p) * 32] = acc[k][p];
}
__device__ __forceinline__ void red_add(ull (&acc)[8][4], const ull* redu, int slotbase) {
    #pragma unroll
    for (int k = 0; k < 8; k++)
        #pragma unroll
        for (int p = 0; p < 4; p++)
            acc[k][p] = addf2(acc[k][p], redu[slotbase + (k * 4 + p) * 32]);
}

// Phase A for a 64-col tile: bits uint2 per row, dup-slot packed Wt writes.
__device__ __forceinline__ void phaseA(const uint2 (&bw)[4], int (&rank)[4],
                                       float (&sacc)[4], ull* WtB,
                                       int w, int lane, unsigned ml) {
    #pragma unroll
    for (int k = 0; k < 4; k++) {
        const int il = 4 * w + k;
        const unsigned b0 = bw[k].x, b1 = bw[k].y;
        const int P0 = __popc(b0);
        const int r0 = rank[k] + __popc(b0 & ml);
        const int r1 = rank[k] + P0 + __popc(b1 & ml);
        rank[k] += P0 + __popc(b1);
        float w0 = 0.f, w1 = 0.f, sl = 0.f;
        if ((b0 >> lane) & 1) { w0 = edgeE(r0); sl += w0; }
        if ((b1 >> lane) & 1) { w1 = edgeE(r1); sl += w1; }
        sacc[k] += sl;
        const ull d0 = packf2(w0, w0), d1 = packf2(w1, w1);
        // c = q*32 + lane; slot = (il + c)&31 = (il + lane)&31 for both q
        ull* wp = WtB + lane * 64 + ((il + lane) & 31);
        wp[0]    = d0; wp[32]        = d0;
        wp[2048] = d1; wp[2048 + 32] = d1;
    }
}

// dynamic smem: Wt[2][64*64] (dup slots, 2x32KB) | hs[2][64*32] (2x16KB) = 96KB
__global__ void __launch_bounds__(256, 2)
k_main(float* __restrict__ out) {
    extern __shared__ ull dsm[];
    ull* Wt0 = dsm;
    ull* Wt1 = dsm + 4096;
    ull* hs0 = dsm + 8192;
    ull* hs1 = dsm + 8192 + 2048;
    __shared__ float sS[32];

    const int tid  = threadIdx.x;
    const int w    = tid >> 5;
    const int lane = tid & 31;
    const int rg   = lane >> 3;
    const int dg   = lane & 7;
    const int row0 = blockIdx.x * 32;
    const unsigned ml = (1u << lane) - 1u;

    // each thread cp.asyncs 64B of the 16KB h tile
    const unsigned hsa0 = (unsigned)__cvta_generic_to_shared(hs0) + tid * 16;
    const unsigned hsa1 = (unsigned)__cvta_generic_to_shared(hs1) + tid * 16;
    const char* hsrc_base = (const char*)g_h + tid * 16;

    int   rank[4];
    float sacc[4];
    #pragma unroll
    for (int k = 0; k < 4; k++) { rank[k] = g_R[row0 + 4 * w + k]; sacc[k] = 0.0f; }

    ull acc[8][4];
    #pragma unroll
    for (int k = 0; k < 8; k++)
        #pragma unroll
        for (int p = 0; p < 4; p++) acc[k][p] = 0ull;

    // ---------------- prologue: h(0) async + PhaseA(0) ----------------
    #pragma unroll
    for (int c = 0; c < 4; c++) cpasync16(hsa0 + c * 4096, hsrc_base + c * 4096);
    CP_COMMIT();
    {
        uint2 bw[4];
        #pragma unroll
        for (int k = 0; k < 4; k++)
            bw[k] = __ldg((const uint2*)(g_bits + (size_t)(row0 + 4 * w + k) * 256));
        phaseA(bw, rank, sacc, Wt0, w, lane, ml);
    }
    CP_WAIT0();
    __syncthreads();

    // ---------------- main pipelined loop: 128 tiles of 64 cols ----------------
    for (int t = 0; t < 128; t++) {
        ull* WtC = (t & 1) ? Wt1 : Wt0;
        ull* hsC = (t & 1) ? hs1 : hs0;
        const int nt = t + 1;
        uint2 bw[4];
        if (nt < 128) {
            // async h(t+1)
            const unsigned dsts = (nt & 1) ? hsa1 : hsa0;
            const char* src = hsrc_base + (size_t)nt * 16384;
            #pragma unroll
            for (int c = 0; c < 4; c++) cpasync16(dsts + c * 4096, src + c * 4096);
            CP_COMMIT();
            // prefetch bits(t+1)
            #pragma unroll
            for (int k = 0; k < 4; k++)
                bw[k] = __ldg((const uint2*)(g_bits + (size_t)(row0 + 4 * w + k) * 256) + nt);
        }

        // ---- Phase B on tile t: out(32x64) += W(32x64) @ h(64x64)
        {
            const ull* hp = hsC + w * 32 + 2 * dg;
            #pragma unroll
            for (int t2 = 0; t2 < 8; t2++) {
                const int j = w + 8 * t2;
                const ull* wp = WtC + j * 64 + ((rg + j) & 31);
                const ulonglong2 hA = *(const ulonglong2*)(hp);
                const ulonglong2 hB = *(const ulonglong2*)(hp + 16);
                #pragma unroll
                for (int k = 0; k < 8; k++) {
                    const ull wv = wp[4 * k];
                    fma2(acc[k][0], wv, hA.x);
                    fma2(acc[k][1], wv, hA.y);
                    fma2(acc[k][2], wv, hB.x);
                    fma2(acc[k][3], wv, hB.y);
                }
                hp += 8 * 32;
            }
        }

        // ---- Phase A for tile t+1 into the other buffer
        if (nt < 128) {
            ull* WtN = (nt & 1) ? Wt1 : Wt0;
            phaseA(bw, rank, sacc, WtN, w, lane, ml);
            CP_WAIT0();
        }
        __syncthreads();
    }

    // ---------------- epilogue ----------------
    #pragma unroll
    for (int k = 0; k < 4; k++) {
        float sv = sacc[k];
        #pragma unroll
        for (int o = 16; o >= 1; o >>= 1) sv += __shfl_xor_sync(0xffffffffu, sv, o);
        if (lane == 0) sS[4 * w + k] = sv;
    }
    __syncthreads();

    ull* redu = dsm;
    if (w >= 4) red_store(acc, redu, (w - 4) * 1024 + lane);
    __syncthreads();
    if (w < 4)  red_add(acc, redu, w * 1024 + lane);
    __syncthreads();
    if (w == 2 || w == 3) red_store(acc, redu, (w - 2) * 1024 + lane);
    __syncthreads();
    if (w < 2)  red_add(acc, redu, w * 1024 + lane);
    __syncthreads();
    if (w == 1) red_store(acc, redu, lane);
    __syncthreads();

    if (w == 0) {
        red_add(acc, redu, lane);
        #pragma unroll
        for (int k = 0; k < 8; k++) {
            const int row = rg + 4 * k;
            const float sinv = 1.0f / sS[row];
            float v[8];
            unpackf2(v[0], v[1], acc[k][0]);
            unpackf2(v[2], v[3], acc[k][1]);
            unpackf2(v[4], v[5], acc[k][2]);
            unpackf2(v[6], v[7], acc[k][3]);
            float o[8];
            #pragma unroll
            for (int c = 0; c < 8; c++) {
                float t = v[c] * sinv;
                o[c] = (t > 0.0f) ? t : expm1f(t);
            }
            float* op = out + (size_t)(row0 + row) * NHID;
            *(float4*)(op + dg * 4)      = make_float4(o[0], o[1], o[2], o[3]);
            *(float4*)(op + 32 + dg * 4) = make_float4(o[4], o[5], o[6], o[7]);
        }
    }
}

extern "C" void kernel_launch(void* const* d_in, const int* in_sizes, int n_in,
                              void* d_out, int out_size) {
    (void)in_sizes; (void)n_in; (void)out_size;
    const float* x   = (const float*)d_in[0];
    const int*   adj = (const int*)d_in[1];
    const float* Ww  = (const float*)d_in[2];
    const float* Wb  = (const float*)d_in[3];
    const float* a1  = (const float*)d_in[4];
    const float* a2  = (const float*)d_in[5];
    const float* ab  = (const float*)d_in[6];
    float* out = (float*)d_out;

    cudaFuncSetAttribute(k_main, cudaFuncAttributeMaxDynamicSharedMemorySize, 98304);

    k_h   <<<NROWS / 16, 256>>>(x, Ww, Wb, a1, a2, ab);
    k_mask<<<NROWS / 8, 256>>>(adj);
    k_scan<<<1, 256>>>();
    k_main<<<NROWS / 32, 256, 98304>>>(out);
}

// round 8
// speedup vs baseline: 1.4460x; 1.2684x over previous
#include <cuda_runtime.h>
#include <cstdint>

#define NROWS 8192
#define NHID  64
#define NEMB  256

__device__ float    g_h[NROWS * NHID];         // [row][d], tf32-rounded values
__device__ float2   g_fsp[NROWS];              // (f_src+b, exp(f_src+b))
__device__ float2   g_fdp[NROWS];              // (f_dst,   exp(f_dst))
__device__ int      g_cnt[NROWS];
__device__ int      g_cnth0[NROWS];
__device__ int      g_R[NROWS];
__device__ unsigned g_bitsT[256 * NROWS];      // [word][row]
__device__ float    g_part[2 * NROWS * NHID];  // [half][row][d]
__device__ float    g_Sp[2 * NROWS];           // [half][row]

// ---------------- helpers ----------------
__device__ __forceinline__ float tf32r(float f) {
    unsigned o;
    asm("cvt.rna.tf32.f32 %0, %1;" : "=r"(o) : "f"(f));
    return __uint_as_float(o);
}
__device__ __forceinline__ void cpasync16(unsigned saddr, const void* gptr) {
    asm volatile("cp.async.cg.shared.global [%0], [%1], 16;" :: "r"(saddr), "l"(gptr));
}
#define CP_COMMIT() asm volatile("cp.async.commit_group;")
#define CP_WAIT0()  asm volatile("cp.async.wait_group 0;")

__device__ __forceinline__ void mma_tf32(float (&c)[4], const float4& a, float b0, float b1) {
    asm("mma.sync.aligned.m16n8k8.row.col.f32.tf32.tf32.f32 "
        "{%0,%1,%2,%3},{%4,%5,%6,%7},{%8,%9},{%0,%1,%2,%3};"
        : "+f"(c[0]), "+f"(c[1]), "+f"(c[2]), "+f"(c[3])
        : "r"(__float_as_uint(a.x)), "r"(__float_as_uint(a.y)),
          "r"(__float_as_uint(a.z)), "r"(__float_as_uint(a.w)),
          "r"(__float_as_uint(b0)), "r"(__float_as_uint(b1)));
}

// ======================= K1: h (tf32-rounded), f tables =======================
__global__ void k_h(const float* __restrict__ x, const float* __restrict__ Ww,
                    const float* __restrict__ Wb, const float* __restrict__ a1,
                    const float* __restrict__ a2, const float* __restrict__ ab) {
    __shared__ float xs[16][NEMB];
    __shared__ float s1[16][2], s2[16][2];
    const int tid = threadIdx.x;
    const int r = tid >> 6, d = tid & 63;
    const int base = blockIdx.x * 16;

    {
        const float4* src = (const float4*)(x + (size_t)base * NEMB);
        float4* dst = (float4*)&xs[0][0];
        #pragma unroll
        for (int t = 0; t < 4; t++) dst[tid + t * 256] = __ldg(src + tid + t * 256);
    }
    __syncthreads();

    const float wb = Wb[d];
    float acc[4] = {wb, wb, wb, wb};
    #pragma unroll 4
    for (int k = 0; k < NEMB; k++) {
        const float wv = __ldg(Ww + k * NHID + d);
        acc[0] = fmaf(xs[r][k],      wv, acc[0]);
        acc[1] = fmaf(xs[r + 4][k],  wv, acc[1]);
        acc[2] = fmaf(xs[r + 8][k],  wv, acc[2]);
        acc[3] = fmaf(xs[r + 12][k], wv, acc[3]);
    }
    const float va1 = __ldg(a1 + d), va2 = __ldg(a2 + d);
    const int half = (tid >> 5) & 1;
    #pragma unroll
    for (int i = 0; i < 4; i++) {
        const int row = base + r + 4 * i;
        g_h[(size_t)row * NHID + d] = tf32r(acc[i]);   // rounded for MMA B-operand
        float v1 = acc[i] * va1, v2 = acc[i] * va2;    // f from full precision
        #pragma unroll
        for (int o = 16; o >= 1; o >>= 1) {
            v1 += __shfl_xor_sync(0xffffffffu, v1, o);
            v2 += __shfl_xor_sync(0xffffffffu, v2, o);
        }
        if ((tid & 31) == 0) { s1[r + 4 * i][half] = v1; s2[r + 4 * i][half] = v2; }
    }
    __syncthreads();
    if (tid < 16) {
        const int row = base + tid;
        float fs = s1[tid][0] + s1[tid][1] + ab[0];
        float fd = s2[tid][0] + s2[tid][1];
        g_fsp[row] = make_float2(fs, expf(fs));
        g_fdp[row] = make_float2(fd, expf(fd));
    }
}

// ======================= K2: transposed bitmask + counts =======================
__global__ void k_mask(const int* __restrict__ adj) {
    const int w = threadIdx.x >> 5, lane = threadIdx.x & 31;
    const int row = blockIdx.x * 8 + w;
    const int* p = adj + (size_t)row * NROWS;
    int c = 0, ch0 = 0;
    #pragma unroll 8
    for (int wi = 0; wi < 256; wi++) {
        unsigned b = __ballot_sync(0xffffffffu, __ldg(p + wi * 32 + lane) > 0);
        if (lane == 0) g_bitsT[(size_t)wi * NROWS + row] = b;
        c += __popc(b);
        if (wi < 128) ch0 += __popc(b);
    }
    if (lane == 0) { g_cnt[row] = c; g_cnth0[row] = ch0; }
}

// ======================= K3: exclusive scan of counts =======================
__global__ void k_scan() {
    __shared__ int sums[256];
    const int t = threadIdx.x;
    const int base = t * 32;
    int tot = 0;
    #pragma unroll
    for (int k = 0; k < 32; k++) tot += g_cnt[base + k];
    sums[t] = tot;
    __syncthreads();
    #pragma unroll
    for (int off = 1; off < 256; off <<= 1) {
        int u = (t >= off) ? sums[t - off] : 0;
        __syncthreads();
        sums[t] += u;
        __syncthreads();
    }
    int run = sums[t] - tot;
    #pragma unroll
    for (int k = 0; k < 32; k++) { int c = g_cnt[base + k]; g_R[base + k] = run; run += c; }
}

// ======================= K4: main kernel (tf32 mma.sync) =======================
__device__ __forceinline__ float edgeE(int rr) {
    float2 a  = __ldg(&g_fsp[rr >> 13]);
    float2 bq = __ldg(&g_fdp[rr & (NROWS - 1)]);
    float s = a.x + bq.x;
    float u = 0.01f * s;
    float p = fmaf(u, 0.0416666679f, 0.1666666716f);
    p = fmaf(p, u, 0.5f);
    p = fmaf(p, u, 1.0f);
    p = fmaf(p, u, 1.0f);
    return (s >= 0.0f) ? a.y * bq.y : p;
}

// Phase A: fill A-fragment tile [64 rows][64 k] for chunk t. Warp w owns rows 8w..8w+7.
__device__ __forceinline__ void phaseA(int t, float* Af, int half, int row0,
                                       int w, int lane, unsigned ml,
                                       int (&rank)[8], float (&sacc)[8]) {
    unsigned myw = 0;
    if (lane < 16)
        myw = __ldg(&g_bitsT[(size_t)(half * 128 + t * 2 + (lane & 1)) * NROWS
                             + row0 + w * 8 + (lane >> 1)]);
    const int tl  = lane & 3;
    const int th2 = ((lane >> 2) & 1) << 1;
    const int kk0 = lane >> 3;                 // 0..3
    const int x0  = kk0 << 2, x1 = (kk0 + 4) << 2;
    #pragma unroll
    for (int i = 0; i < 8; i++) {
        const int row = w * 8 + i;
        const int g = row & 7, hi = (row >> 3) & 1, mtile = row >> 4;
        const unsigned b0 = __shfl_sync(0xffffffffu, myw, 2 * i);
        const unsigned b1 = __shfl_sync(0xffffffffu, myw, 2 * i + 1);
        const int c0 = __popc(b0);
        const int rb = rank[i];
        rank[i] = rb + c0 + __popc(b1);
        float w0 = 0.f, w1 = 0.f;
        if ((b0 >> lane) & 1) { w0 = tf32r(edgeE(rb + __popc(b0 & ml)));      sacc[i] += w0; }
        if ((b1 >> lane) & 1) { w1 = tf32r(edgeE(rb + c0 + __popc(b1 & ml))); sacc[i] += w1; }
        const int base = g * 4 + tl;
        const int mb = mtile * 1024 + hi + th2;
        Af[mb + kk0 * 128 + ((base ^ x0) << 2)]       = w0;
        Af[mb + (kk0 + 4) * 128 + ((base ^ x1) << 2)] = w1;
    }
}

// Phase B: warp-tile (mi: 32 rows, nj: 32 cols, kh: 32 k of the 64-k chunk)
__device__ __forceinline__ void phaseB(const float* Af, const float* hs,
                                       float (&acc)[2][4][4],
                                       int mi, int nj, int kh, int lane) {
    const int tl = lane & 3, gq = lane >> 2;
    #pragma unroll
    for (int k8 = 0; k8 < 4; k8++) {
        const int kk = kh * 4 + k8;
        const int fl = lane ^ (kk << 2);
        const float4 a0 = *(const float4*)(Af + ((mi * 2) * 8 + kk) * 128 + fl * 4);
        const float4 a1 = *(const float4*)(Af + ((mi * 2 + 1) * 8 + kk) * 128 + fl * 4);
        const float* hb = hs + (kk * 8 + tl) * 68 + nj * 32 + gq;
        float b0[4], b1[4];
        #pragma unroll
        for (int n8 = 0; n8 < 4; n8++) {
            b0[n8] = hb[n8 * 8];
            b1[n8] = hb[n8 * 8 + 4 * 68];
        }
        #pragma unroll
        for (int n8 = 0; n8 < 4; n8++) {
            mma_tf32(acc[0][n8], a0, b0[n8], b1[n8]);
            mma_tf32(acc[1][n8], a1, b0[n8], b1[n8]);
        }
    }
}

// dynamic smem: Af[2] 2x16KB | hs[2] 2x17408B  = 67584B
__global__ void __launch_bounds__(256, 2)
k_main() {
    extern __shared__ float dsm[];
    float* Af[2] = {dsm, dsm + 4096};
    float* hs[2] = {dsm + 8192, dsm + 8192 + 4352};

    const int tid  = threadIdx.x;
    const int w    = tid >> 5;
    const int lane = tid & 31;
    const int half = blockIdx.x & 1;
    const int row0 = (blockIdx.x >> 1) * 64;
    const unsigned ml = (1u << lane) - 1u;
    // Phase-B warp roles
    const int kh = w & 1, mi = (w >> 1) & 1, nj = w >> 2;

    const unsigned hsa[2] = {
        (unsigned)__cvta_generic_to_shared(hs[0]) ,
        (unsigned)__cvta_generic_to_shared(hs[1]) };

    int   rank[8];
    float sacc[8];
    #pragma unroll
    for (int i = 0; i < 8; i++) {
        const int row = row0 + w * 8 + i;
        rank[i] = __ldg(&g_R[row]) + (half ? __ldg(&g_cnth0[row]) : 0);
        sacc[i] = 0.0f;
    }

    float acc[2][4][4];
    #pragma unroll
    for (int m = 0; m < 2; m++)
        #pragma unroll
        for (int n = 0; n < 4; n++)
            #pragma unroll
            for (int p = 0; p < 4; p++) acc[m][n][p] = 0.0f;

    const int kbase = half * 4096;
    #define LOAD_B(T, BUF) do {                                                 \
        const int kg = kbase + (T) * 64;                                        \
        _Pragma("unroll")                                                       \
        for (int c = 0; c < 4; c++) {                                           \
            const int id = tid + 256 * c;                                       \
            const int rr = id >> 4, oo = id & 15;                               \
            cpasync16(hsa[BUF] + rr * 272 + oo * 16,                            \
                      g_h + (size_t)(kg + rr) * 64 + oo * 4);                   \
        }                                                                       \
        CP_COMMIT();                                                            \
    } while (0)

    // prologue
    LOAD_B(0, 0);
    phaseA(0, Af[0], half, row0, w, lane, ml, rank, sacc);
    CP_WAIT0();
    __syncthreads();

    for (int t = 0; t < 64; t++) {
        const int cur = t & 1, nxt = cur ^ 1;
        if (t + 1 < 64) LOAD_B(t + 1, nxt);
        phaseB(Af[cur], hs[cur], acc, mi, nj, kh, lane);
        if (t + 1 < 64) {
            phaseA(t + 1, Af[nxt], half, row0, w, lane, ml, rank, sacc);
            CP_WAIT0();
        }
        __syncthreads();
    }

    // ---- denominators ----
    #pragma unroll
    for (int i = 0; i < 8; i++) {
        float sv = sacc[i];
        #pragma unroll
        for (int o = 16; o >= 1; o >>= 1) sv += __shfl_xor_sync(0xffffffffu, sv, o);
        if (lane == 0) g_Sp[half * NROWS + row0 + w * 8 + i] = sv;
    }
    __syncthreads();

    // ---- combine kh halves via smem (reuse Af region) ----
    float4* red = (float4*)dsm;
    const int slot = ((mi * 2 + nj) * 32 + lane) * 8;
    if (kh == 1) {
        #pragma unroll
        for (int m = 0; m < 2; m++)
            #pragma unroll
            for (int n = 0; n < 4; n++)
                red[slot + m * 4 + n] = make_float4(acc[m][n][0], acc[m][n][1],
                                                    acc[m][n][2], acc[m][n][3]);
    }
    __syncthreads();
    if (kh == 0) {
        const int tl = lane & 3, gq = lane >> 2;
        #pragma unroll
        for (int m = 0; m < 2; m++) {
            const int grow = row0 + mi * 32 + m * 16 + gq;
            #pragma unroll
            for (int n = 0; n < 4; n++) {
                const float4 v = red[slot + m * 4 + n];
                const int col = nj * 32 + n * 8 + tl * 2;
                float2 lo = make_float2(acc[m][n][0] + v.x, acc[m][n][1] + v.y);
                float2 hi2 = make_float2(acc[m][n][2] + v.z, acc[m][n][3] + v.w);
                *(float2*)(g_part + ((size_t)half * NROWS + grow) * 64 + col) = lo;
                *(float2*)(g_part + ((size_t)half * NROWS + grow + 8) * 64 + col) = hi2;
            }
        }
    }
}

// ======================= K5: combine K-halves + softmax divide + elu =======================
__global__ void k_comb(float* __restrict__ out) {
    const int idx = blockIdx.x * 256 + threadIdx.x;  // float4 index
    const int row = idx >> 4;
    const int c4  = idx & 15;
    const float4 p0 = *(const float4*)(g_part + (size_t)row * NHID + c4 * 4);
    const float4 p1 = *(const float4*)(g_part + (size_t)(NROWS + row) * NHID + c4 * 4);
    const float sinv = 1.0f / (g_Sp[row] + g_Sp[NROWS + row]);
    float v[4] = {(p0.x + p1.x) * sinv, (p0.y + p1.y) * sinv,
                  (p0.z + p1.z) * sinv, (p0.w + p1.w) * sinv};
    #pragma unroll
    for (int c = 0; c < 4; c++) v[c] = (v[c] > 0.0f) ? v[c] : expm1f(v[c]);
    *(float4*)(out + (size_t)row * NHID + c4 * 4) = make_float4(v[0], v[1], v[2], v[3]);
}

extern "C" void kernel_launch(void* const* d_in, const int* in_sizes, int n_in,
                              void* d_out, int out_size) {
    (void)in_sizes; (void)n_in; (void)out_size;
    const float* x   = (const float*)d_in[0];
    const int*   adj = (const int*)d_in[1];
    const float* Ww  = (const float*)d_in[2];
    const float* Wb  = (const float*)d_in[3];
    const float* a1  = (const float*)d_in[4];
    const float* a2  = (const float*)d_in[5];
    const float* ab  = (const float*)d_in[6];
    float* out = (float*)d_out;

    cudaFuncSetAttribute(k_main, cudaFuncAttributeMaxDynamicSharedMemorySize, 67584);

    k_h   <<<NROWS / 16, 256>>>(x, Ww, Wb, a1, a2, ab);
    k_mask<<<NROWS / 8, 256>>>(adj);
    k_scan<<<1, 256>>>();
    k_main<<<256, 256, 67584>>>();
    k_comb<<<NROWS * NHID / 1024, 256>>>(out);
}

// round 9
// speedup vs baseline: 1.5490x; 1.0712x over previous
#include <cuda_runtime.h>
#include <cstdint>

#define NROWS 8192
#define NHID  64
#define NEMB  256

__device__ float    g_h[NROWS * NHID];         // [row][d], tf32-rounded
__device__ float2   g_fsp[NROWS];              // (f_src+b, exp(f_src+b))
__device__ float2   g_fdp[NROWS];              // (f_dst,   exp(f_dst))
__device__ int      g_cnt[NROWS];
__device__ int      g_cnth0[NROWS];
__device__ int      g_R[NROWS];
__device__ unsigned g_bits[NROWS * 256];       // row-major: [row][word], word = col/32
__device__ float    g_part[2 * NROWS * NHID];  // [half][row][d]
__device__ float    g_Sp[2 * NROWS];           // [half][row]

// ---------------- helpers ----------------
__device__ __forceinline__ float tf32r(float f) {
    unsigned o;
    asm("cvt.rna.tf32.f32 %0, %1;" : "=r"(o) : "f"(f));
    return __uint_as_float(o);
}
__device__ __forceinline__ void cpasync16(unsigned saddr, const void* gptr) {
    asm volatile("cp.async.cg.shared.global [%0], [%1], 16;" :: "r"(saddr), "l"(gptr));
}
__device__ __forceinline__ void cpasync8(unsigned saddr, const void* gptr) {
    asm volatile("cp.async.ca.shared.global [%0], [%1], 8;" :: "r"(saddr), "l"(gptr));
}
#define CP_COMMIT() asm volatile("cp.async.commit_group;")
#define CP_WAIT0()  asm volatile("cp.async.wait_group 0;")

__device__ __forceinline__ void mma_tf32(float (&c)[4], const float4& a, float b0, float b1) {
    asm("mma.sync.aligned.m16n8k8.row.col.f32.tf32.tf32.f32 "
        "{%0,%1,%2,%3},{%4,%5,%6,%7},{%8,%9},{%0,%1,%2,%3};"
        : "+f"(c[0]), "+f"(c[1]), "+f"(c[2]), "+f"(c[3])
        : "r"(__float_as_uint(a.x)), "r"(__float_as_uint(a.y)),
          "r"(__float_as_uint(a.z)), "r"(__float_as_uint(a.w)),
          "r"(__float_as_uint(b0)), "r"(__float_as_uint(b1)));
}

// ======================= K1: h (tf32-rounded), f tables =======================
__global__ void k_h(const float* __restrict__ x, const float* __restrict__ Ww,
                    const float* __restrict__ Wb, const float* __restrict__ a1,
                    const float* __restrict__ a2, const float* __restrict__ ab) {
    __shared__ float xs[16][NEMB];
    __shared__ float s1[16][2], s2[16][2];
    const int tid = threadIdx.x;
    const int r = tid >> 6, d = tid & 63;
    const int base = blockIdx.x * 16;

    {
        const float4* src = (const float4*)(x + (size_t)base * NEMB);
        float4* dst = (float4*)&xs[0][0];
        #pragma unroll
        for (int t = 0; t < 4; t++) dst[tid + t * 256] = __ldg(src + tid + t * 256);
    }
    __syncthreads();

    const float wb = Wb[d];
    float acc[4] = {wb, wb, wb, wb};
    #pragma unroll 4
    for (int k = 0; k < NEMB; k++) {
        const float wv = __ldg(Ww + k * NHID + d);
        acc[0] = fmaf(xs[r][k],      wv, acc[0]);
        acc[1] = fmaf(xs[r + 4][k],  wv, acc[1]);
        acc[2] = fmaf(xs[r + 8][k],  wv, acc[2]);
        acc[3] = fmaf(xs[r + 12][k], wv, acc[3]);
    }
    const float va1 = __ldg(a1 + d), va2 = __ldg(a2 + d);
    const int half = (tid >> 5) & 1;
    #pragma unroll
    for (int i = 0; i < 4; i++) {
        const int row = base + r + 4 * i;
        g_h[(size_t)row * NHID + d] = tf32r(acc[i]);
        float v1 = acc[i] * va1, v2 = acc[i] * va2;
        #pragma unroll
        for (int o = 16; o >= 1; o >>= 1) {
            v1 += __shfl_xor_sync(0xffffffffu, v1, o);
            v2 += __shfl_xor_sync(0xffffffffu, v2, o);
        }
        if ((tid & 31) == 0) { s1[r + 4 * i][half] = v1; s2[r + 4 * i][half] = v2; }
    }
    __syncthreads();
    if (tid < 16) {
        const int row = base + tid;
        float fs = s1[tid][0] + s1[tid][1] + ab[0];
        float fd = s2[tid][0] + s2[tid][1];
        g_fsp[row] = make_float2(fs, expf(fs));
        g_fdp[row] = make_float2(fd, expf(fd));
    }
}

// ======================= K2: row-major bitmask + counts =======================
__global__ void k_mask(const int* __restrict__ adj) {
    const int w = threadIdx.x >> 5, lane = threadIdx.x & 31;
    const int row = blockIdx.x * 8 + w;
    const int* p = adj + (size_t)row * NROWS;
    int c = 0, ch0 = 0;
    #pragma unroll 2
    for (int ch = 0; ch < 64; ch++) {
        unsigned b[4];
        #pragma unroll
        for (int q = 0; q < 4; q++)
            b[q] = __ballot_sync(0xffffffffu, __ldg(p + ch * 128 + q * 32 + lane) > 0);
        if (lane == 0)
            *(uint4*)(g_bits + (size_t)row * 256 + ch * 4) = make_uint4(b[0], b[1], b[2], b[3]);
        const int s = __popc(b[0]) + __popc(b[1]) + __popc(b[2]) + __popc(b[3]);
        c += s;
        if (ch < 32) ch0 += s;
    }
    if (lane == 0) { g_cnt[row] = c; g_cnth0[row] = ch0; }
}

// ======================= K3: exclusive scan of counts =======================
__global__ void k_scan() {
    __shared__ int sums[256];
    const int t = threadIdx.x;
    const int base = t * 32;
    int tot = 0;
    #pragma unroll
    for (int k = 0; k < 32; k++) tot += g_cnt[base + k];
    sums[t] = tot;
    __syncthreads();
    #pragma unroll
    for (int off = 1; off < 256; off <<= 1) {
        int u = (t >= off) ? sums[t - off] : 0;
        __syncthreads();
        sums[t] += u;
        __syncthreads();
    }
    int run = sums[t] - tot;
    #pragma unroll
    for (int k = 0; k < 32; k++) { int c = g_cnt[base + k]; g_R[base + k] = run; run += c; }
}

// ======================= K4: main kernel (tf32 mma.sync) =======================
__device__ __forceinline__ float edgeE(int rr) {
    float2 a  = __ldg(&g_fsp[rr >> 13]);
    float2 bq = __ldg(&g_fdp[rr & (NROWS - 1)]);
    float s = a.x + bq.x;
    float u = 0.01f * s;
    float p = fmaf(u, 0.0416666679f, 0.1666666716f);
    p = fmaf(p, u, 0.5f);
    p = fmaf(p, u, 1.0f);
    p = fmaf(p, u, 1.0f);
    return (s >= 0.0f) ? a.y * bq.y : p;
}

// Phase A: fill A-fragment tile [64 rows][64 k]. Warp w owns rows 8w..8w+7.
// Bits come from smem (cp.async-staged, broadcast LDS.64) — no shfl, no LDG.
__device__ __forceinline__ void phaseA(const uint2* __restrict__ sb, float* __restrict__ Af,
                                       int w, int lane, unsigned ml,
                                       int (&rank)[8], float (&sacc)[8]) {
    const int tl  = lane & 3;
    const int th2 = ((lane >> 2) & 1) << 1;
    const int kk0 = lane >> 3;
    const int x0  = kk0 << 2, x1 = (kk0 + 4) << 2;
    #pragma unroll
    for (int i = 0; i < 8; i++) {
        const int row = w * 8 + i;
        const uint2 bw = sb[row];
        const unsigned b0 = bw.x, b1 = bw.y;
        const int c0 = __popc(b0);
        const int rb = rank[i];
        rank[i] = rb + c0 + __popc(b1);
        float w0 = 0.f, w1 = 0.f;
        if ((b0 >> lane) & 1) { w0 = tf32r(edgeE(rb + __popc(b0 & ml)));      sacc[i] += w0; }
        if ((b1 >> lane) & 1) { w1 = tf32r(edgeE(rb + c0 + __popc(b1 & ml))); sacc[i] += w1; }
        const int g = row & 7, hi = (row >> 3) & 1, mtile = row >> 4;
        const int base = g * 4 + tl;
        const int mb = mtile * 1024 + hi + th2;
        Af[mb + kk0 * 128 + ((base ^ x0) << 2)]       = w0;
        Af[mb + (kk0 + 4) * 128 + ((base ^ x1) << 2)] = w1;
    }
}

// Phase B: warp-tile (mi: 32 rows, nj: 32 cols, kh: 32 k of the 64-k chunk)
__device__ __forceinline__ void phaseB(const float* __restrict__ Af, const float* __restrict__ hs,
                                       float (&acc)[2][4][4],
                                       int mi, int nj, int kh, int lane) {
    const int tl = lane & 3, gq = lane >> 2;
    #pragma unroll
    for (int k8 = 0; k8 < 4; k8++) {
        const int kk = kh * 4 + k8;
        const int fl = lane ^ (kk << 2);
        const float4 a0 = *(const float4*)(Af + ((mi * 2) * 8 + kk) * 128 + fl * 4);
        const float4 a1 = *(const float4*)(Af + ((mi * 2 + 1) * 8 + kk) * 128 + fl * 4);
        const float* hb = hs + (kk * 8 + tl) * 72 + nj * 32 + gq;  // stride 72: conflict-free
        float b0[4], b1[4];
        #pragma unroll
        for (int n8 = 0; n8 < 4; n8++) {
            b0[n8] = hb[n8 * 8];
            b1[n8] = hb[n8 * 8 + 4 * 72];
        }
        #pragma unroll
        for (int n8 = 0; n8 < 4; n8++) {
            mma_tf32(acc[0][n8], a0, b0[n8], b1[n8]);
            mma_tf32(acc[1][n8], a1, b0[n8], b1[n8]);
        }
    }
}

// dynamic smem (floats): Af[2] 2x4096 | hs[2] 2x4608 (64 rows x 72) | sbits[2] 2x128
// total 17664 floats = 70656 B ; 2 CTAs/SM = 141 KB < 227 KB
__global__ void __launch_bounds__(256, 2)
k_main() {
    extern __shared__ float dsm[];
    float* Af[2] = {dsm, dsm + 4096};
    float* hs[2] = {dsm + 8192, dsm + 8192 + 4608};
    uint2* sbits[2] = {(uint2*)(dsm + 17408), (uint2*)(dsm + 17536)};

    const int tid  = threadIdx.x;
    const int w    = tid >> 5;
    const int lane = tid & 31;
    const int half = blockIdx.x & 1;
    const int row0 = (blockIdx.x >> 1) * 64;
    const unsigned ml = (1u << lane) - 1u;
    const int kh = w & 1, mi = (w >> 1) & 1, nj = w >> 2;

    const unsigned hsa[2] = {
        (unsigned)__cvta_generic_to_shared(hs[0]),
        (unsigned)__cvta_generic_to_shared(hs[1]) };
    const unsigned sba[2] = {
        (unsigned)__cvta_generic_to_shared(sbits[0]),
        (unsigned)__cvta_generic_to_shared(sbits[1]) };

    int   rank[8];
    float sacc[8];
    #pragma unroll
    for (int i = 0; i < 8; i++) {
        const int row = row0 + w * 8 + i;
        rank[i] = __ldg(&g_R[row]) + (half ? __ldg(&g_cnth0[row]) : 0);
        sacc[i] = 0.0f;
    }

    float acc[2][4][4];
    #pragma unroll
    for (int m = 0; m < 2; m++)
        #pragma unroll
        for (int n = 0; n < 4; n++)
            #pragma unroll
            for (int p = 0; p < 4; p++) acc[m][n][p] = 0.0f;

    const int kbase = half * 4096;
    #define LOAD_B(T, BUF) do {                                                 \
        const int kg = kbase + (T) * 64;                                        \
        _Pragma("unroll")                                                       \
        for (int c = 0; c < 4; c++) {                                           \
            const int id = tid + 256 * c;                                       \
            const int rr = id >> 4, oo = id & 15;                               \
            cpasync16(hsa[BUF] + rr * 288 + oo * 16,                            \
                      g_h + (size_t)(kg + rr) * 64 + oo * 4);                   \
        }                                                                       \
    } while (0)

    #define LOAD_BITS(T, BUF) do {                                              \
        if (tid < 64)                                                           \
            cpasync8(sba[BUF] + tid * 8,                                        \
                     g_bits + (size_t)(row0 + tid) * 256 + half * 128 + 2 * (T)); \
    } while (0)

    // -------- prologue --------
    LOAD_B(0, 0);
    LOAD_BITS(0, 0);
    LOAD_BITS(1, 1);
    CP_COMMIT();
    CP_WAIT0();
    __syncthreads();
    phaseA(sbits[0], Af[0], w, lane, ml, rank, sacc);
    __syncthreads();

    // -------- main loop --------
    for (int t = 0; t < 64; t++) {
        const int cur = t & 1, nxt = cur ^ 1;
        if (t + 1 < 64) LOAD_B(t + 1, nxt);
        if (t + 2 < 64) LOAD_BITS(t + 2, cur);   // bits(T) live in buffer T&1
        CP_COMMIT();
        phaseB(Af[cur], hs[cur], acc, mi, nj, kh, lane);
        if (t + 1 < 64)
            phaseA(sbits[nxt], Af[nxt], w, lane, ml, rank, sacc);
        CP_WAIT0();
        __syncthreads();
    }

    // ---- denominators ----
    #pragma unroll
    for (int i = 0; i < 8; i++) {
        float sv = sacc[i];
        #pragma unroll
        for (int o = 16; o >= 1; o >>= 1) sv += __shfl_xor_sync(0xffffffffu, sv, o);
        if (lane == 0) g_Sp[half * NROWS + row0 + w * 8 + i] = sv;
    }
    __syncthreads();

    // ---- combine kh halves via smem (reuse Af region) ----
    float4* red = (float4*)dsm;
    const int slot = ((mi * 2 + nj) * 32 + lane) * 8;
    if (kh == 1) {
        #pragma unroll
        for (int m = 0; m < 2; m++)
            #pragma unroll
            for (int n = 0; n < 4; n++)
                red[slot + m * 4 + n] = make_float4(acc[m][n][0], acc[m][n][1],
                                                    acc[m][n][2], acc[m][n][3]);
    }
    __syncthreads();
    if (kh == 0) {
        const int tl = lane & 3, gq = lane >> 2;
        #pragma unroll
        for (int m = 0; m < 2; m++) {
            const int grow = row0 + mi * 32 + m * 16 + gq;
            #pragma unroll
            for (int n = 0; n < 4; n++) {
                const float4 v = red[slot + m * 4 + n];
                const int col = nj * 32 + n * 8 + tl * 2;
                float2 lo  = make_float2(acc[m][n][0] + v.x, acc[m][n][1] + v.y);
                float2 hi2 = make_float2(acc[m][n][2] + v.z, acc[m][n][3] + v.w);
                *(float2*)(g_part + ((size_t)half * NROWS + grow) * 64 + col) = lo;
                *(float2*)(g_part + ((size_t)half * NROWS + grow + 8) * 64 + col) = hi2;
            }
        }
    }
}

// ======================= K5: combine K-halves + softmax divide + elu =======================
__global__ void k_comb(float* __restrict__ out) {
    const int idx = blockIdx.x * 256 + threadIdx.x;
    const int row = idx >> 4;
    const int c4  = idx & 15;
    const float4 p0 = *(const float4*)(g_part + (size_t)row * NHID + c4 * 4);
    const float4 p1 = *(const float4*)(g_part + (size_t)(NROWS + row) * NHID + c4 * 4);
    const float sinv = 1.0f / (g_Sp[row] + g_Sp[NROWS + row]);
    float v[4] = {(p0.x + p1.x) * sinv, (p0.y + p1.y) * sinv,
                  (p0.z + p1.z) * sinv, (p0.w + p1.w) * sinv};
    #pragma unroll
    for (int c = 0; c < 4; c++) v[c] = (v[c] > 0.0f) ? v[c] : expm1f(v[c]);
    *(float4*)(out + (size_t)row * NHID + c4 * 4) = make_float4(v[0], v[1], v[2], v[3]);
}

extern "C" void kernel_launch(void* const* d_in, const int* in_sizes, int n_in,
                              void* d_out, int out_size) {
    (void)in_sizes; (void)n_in; (void)out_size;
    const float* x   = (const float*)d_in[0];
    const int*   adj = (const int*)d_in[1];
    const float* Ww  = (const float*)d_in[2];
    const float* Wb  = (const float*)d_in[3];
    const float* a1  = (const float*)d_in[4];
    const float* a2  = (const float*)d_in[5];
    const float* ab  = (const float*)d_in[6];
    float* out = (float*)d_out;

    cudaFuncSetAttribute(k_main, cudaFuncAttributeMaxDynamicSharedMemorySize, 70656);

    k_h   <<<NROWS / 16, 256>>>(x, Ww, Wb, a1, a2, ab);
    k_mask<<<NROWS / 8, 256>>>(adj);
    k_scan<<<1, 256>>>();
    k_main<<<256, 256, 70656>>>();
    k_comb<<<NROWS * NHID / 1024, 256>>>(out);
}